// round 1
// baseline (speedup 1.0000x reference)
#include <cuda_runtime.h>
#include <math.h>

#define B_   8
#define N_   4096
#define C_   768
#define H_   12
#define D_   64
#define C3_  2304
#define BH_  (B_*H_)          // 96
#define NSPLIT 4
#define TOK_PER_SPLIT (N_/NSPLIT) // 1024

// ---- scratch (device globals; no runtime allocation allowed) ----
__device__ float g_attn_part[NSPLIT][BH_][D_][D_];   // 6.3 MB
__device__ float g_qnorm_part[NSPLIT][BH_][D_];
__device__ float g_attn[BH_][D_][D_];                // softmaxed attention
__device__ float g_y[(size_t)B_*N_*C_];              // ~100.7 MB intermediate

// ============================================================
// Kernel 1: per (b,h,split): attn_part = q @ khat^T  (+ Σq² partials)
//   q[n,i] = x[b,n, 0*C + h*64 + i]
//   k[n,j] = x[b,n, 1*C + h*64 + j], normalized over j (d=64) on the fly
// ============================================================
__global__ void __launch_bounds__(256) qk_kernel(const float* __restrict__ x) {
    const int bh    = blockIdx.x;
    const int b     = bh / H_;
    const int h     = bh % H_;
    const int split = blockIdx.y;
    const int t     = threadIdx.x;

    const int nl = t >> 4;       // token-in-chunk for loading (0..15)
    const int j4 = t & 15;       // float4 index within 64 (0..15)
    const int ti = t & 15;       // output i-quad
    const int tj = t >> 4;       // output j-quad

    __shared__ float qs[16][64];
    __shared__ float ks[16][64];

    float4 qsq = make_float4(0.f, 0.f, 0.f, 0.f);
    float acc[4][4];
    #pragma unroll
    for (int a = 0; a < 4; a++)
        #pragma unroll
        for (int c = 0; c < 4; c++) acc[a][c] = 0.f;

    const float* xb = x + (size_t)b * N_ * C3_ + h * D_;
    const int nbeg = split * TOK_PER_SPLIT;

    for (int n0 = nbeg; n0 < nbeg + TOK_PER_SPLIT; n0 += 16) {
        const float* row = xb + (size_t)(n0 + nl) * C3_;
        float4 q4 = *(const float4*)(row + j4 * 4);
        float4 k4 = *(const float4*)(row + C_ + j4 * 4);

        // k row norm over d=64: reduce across the 16 lanes sharing this token
        float s = k4.x*k4.x + k4.y*k4.y + k4.z*k4.z + k4.w*k4.w;
        s += __shfl_xor_sync(0xffffffffu, s, 1);
        s += __shfl_xor_sync(0xffffffffu, s, 2);
        s += __shfl_xor_sync(0xffffffffu, s, 4);
        s += __shfl_xor_sync(0xffffffffu, s, 8);
        float inv = 1.0f / fmaxf(sqrtf(s), 1e-12f);
        k4.x *= inv; k4.y *= inv; k4.z *= inv; k4.w *= inv;

        qsq.x += q4.x*q4.x; qsq.y += q4.y*q4.y;
        qsq.z += q4.z*q4.z; qsq.w += q4.w*q4.w;

        __syncthreads();   // prior chunk fully consumed
        *(float4*)&qs[nl][j4 * 4] = q4;
        *(float4*)&ks[nl][j4 * 4] = k4;
        __syncthreads();

        #pragma unroll
        for (int nn = 0; nn < 16; nn++) {
            float4 aq = *(const float4*)&qs[nn][ti * 4];
            float4 bk = *(const float4*)&ks[nn][tj * 4];
            float aa[4] = {aq.x, aq.y, aq.z, aq.w};
            float bb[4] = {bk.x, bk.y, bk.z, bk.w};
            #pragma unroll
            for (int ii = 0; ii < 4; ii++)
                #pragma unroll
                for (int jj = 0; jj < 4; jj++)
                    acc[ii][jj] = fmaf(aa[ii], bb[jj], acc[ii][jj]);
        }
    }

    // write attention partial
    #pragma unroll
    for (int ii = 0; ii < 4; ii++)
        #pragma unroll
        for (int jj = 0; jj < 4; jj++)
            g_attn_part[split][bh][ti * 4 + ii][tj * 4 + jj] = acc[ii][jj];

    // reduce q-square partials (i = j4*4 + {0..3})
    __shared__ float qn[64];
    if (t < 64) qn[t] = 0.f;
    __syncthreads();
    atomicAdd(&qn[j4 * 4 + 0], qsq.x);
    atomicAdd(&qn[j4 * 4 + 1], qsq.y);
    atomicAdd(&qn[j4 * 4 + 2], qsq.z);
    atomicAdd(&qn[j4 * 4 + 3], qsq.w);
    __syncthreads();
    if (t < 64) g_qnorm_part[split][bh][t] = qn[t];
}

// ============================================================
// Kernel 2: reduce partials, apply 1/qnorm and temperature, row softmax
// ============================================================
__global__ void __launch_bounds__(64) softmax_kernel(const float* __restrict__ temp) {
    const int bh = blockIdx.x;
    const int h  = bh % H_;
    const int i  = threadIdx.x;

    float qn2 = 0.f;
    #pragma unroll
    for (int s = 0; s < NSPLIT; s++) qn2 += g_qnorm_part[s][bh][i];
    const float invq   = 1.0f / fmaxf(sqrtf(qn2), 1e-12f);
    const float tscale = temp[h] * invq;

    float v[64];
    float mx = -1e30f;
    #pragma unroll
    for (int j = 0; j < 64; j++) {
        float a = 0.f;
        #pragma unroll
        for (int s = 0; s < NSPLIT; s++) a += g_attn_part[s][bh][i][j];
        a *= tscale;
        v[j] = a;
        mx = fmaxf(mx, a);
    }
    float sum = 0.f;
    #pragma unroll
    for (int j = 0; j < 64; j++) { v[j] = expf(v[j] - mx); sum += v[j]; }
    const float r = 1.0f / sum;
    #pragma unroll
    for (int j = 0; j < 64; j++) g_attn[bh][i][j] = v[j] * r;
}

// ============================================================
// Kernel 3: y[b,n, h*64+i] = Σ_j attn[bh,i,j] * v[b,n,h,j]
//   v[n,j] = x[b,n, 2*C + h*64 + j]
//   One block per (bh, 64-token tile).
// ============================================================
__global__ void __launch_bounds__(256) av_kernel(const float* __restrict__ x) {
    const int bh = blockIdx.y;
    const int b  = bh / H_;
    const int h  = bh % H_;
    const int n0 = blockIdx.x * 64;
    const int t  = threadIdx.x;

    __shared__ float asT[64][68];   // asT[j][i] = attn[i][j]
    __shared__ float vs[64][68];    // vs[n][j]

    for (int idx = t; idx < 4096; idx += 256) {
        int i = idx >> 6, j = idx & 63;
        asT[j][i] = g_attn[bh][i][j];
    }

    const int j4 = t & 15;
    const int nb = t >> 4;
    const float* xv = x + (size_t)b * N_ * C3_ + 2 * C_ + h * D_;
    #pragma unroll
    for (int r = 0; r < 4; r++) {
        int n = nb + r * 16;
        *(float4*)&vs[n][j4 * 4] =
            *(const float4*)(xv + (size_t)(n0 + n) * C3_ + j4 * 4);
    }
    __syncthreads();

    const int ti = t & 15;   // i-quad
    const int tn = t >> 4;   // n-quad
    float acc[4][4];
    #pragma unroll
    for (int a = 0; a < 4; a++)
        #pragma unroll
        for (int c = 0; c < 4; c++) acc[a][c] = 0.f;

    #pragma unroll 8
    for (int j = 0; j < 64; j++) {
        float4 a = *(const float4*)&asT[j][ti * 4];
        float aa[4] = {a.x, a.y, a.z, a.w};
        float vv[4];
        #pragma unroll
        for (int nn = 0; nn < 4; nn++) vv[nn] = vs[tn * 4 + nn][j];
        #pragma unroll
        for (int nn = 0; nn < 4; nn++)
            #pragma unroll
            for (int ii = 0; ii < 4; ii++)
                acc[nn][ii] = fmaf(vv[nn], aa[ii], acc[nn][ii]);
    }

    #pragma unroll
    for (int nn = 0; nn < 4; nn++) {
        int n = n0 + tn * 4 + nn;
        float4 o = make_float4(acc[nn][0], acc[nn][1], acc[nn][2], acc[nn][3]);
        *(float4*)(g_y + ((size_t)b * N_ + n) * C_ + h * D_ + ti * 4) = o;
    }
}

// ============================================================
// Kernel 4: out = Y @ W^T + bias   ([32768 x 768] x [768 x 768])
//   Block tile 128x128, k-step 8, 8x8 register tiles, 256 threads.
// ============================================================
__global__ void __launch_bounds__(256) proj_kernel(const float* __restrict__ w,
                                                   const float* __restrict__ bias,
                                                   float* __restrict__ out) {
    __shared__ float ysT[8][132];
    __shared__ float wsT[8][132];

    const int r0 = blockIdx.y * 128;
    const int c0 = blockIdx.x * 128;
    const int t  = threadIdx.x;
    const int tr = t & 15;        // row-octet
    const int tc = t >> 4;        // col-octet
    const int lr = t >> 1;        // load row (0..127)
    const int lk = (t & 1) * 4;   // load k offset (0 or 4)

    float acc[8][8];
    #pragma unroll
    for (int i = 0; i < 8; i++)
        #pragma unroll
        for (int j = 0; j < 8; j++) acc[i][j] = 0.f;

    for (int k0 = 0; k0 < C_; k0 += 8) {
        float4 yv = *(const float4*)(g_y + (size_t)(r0 + lr) * C_ + k0 + lk);
        float4 wv = *(const float4*)(w   + (size_t)(c0 + lr) * C_ + k0 + lk);
        __syncthreads();
        ysT[lk + 0][lr] = yv.x; ysT[lk + 1][lr] = yv.y;
        ysT[lk + 2][lr] = yv.z; ysT[lk + 3][lr] = yv.w;
        wsT[lk + 0][lr] = wv.x; wsT[lk + 1][lr] = wv.y;
        wsT[lk + 2][lr] = wv.z; wsT[lk + 3][lr] = wv.w;
        __syncthreads();

        #pragma unroll
        for (int k = 0; k < 8; k++) {
            float a[8], bv[8];
            *(float4*)&a[0]  = *(const float4*)&ysT[k][tr * 8];
            *(float4*)&a[4]  = *(const float4*)&ysT[k][tr * 8 + 4];
            *(float4*)&bv[0] = *(const float4*)&wsT[k][tc * 8];
            *(float4*)&bv[4] = *(const float4*)&wsT[k][tc * 8 + 4];
            #pragma unroll
            for (int i = 0; i < 8; i++)
                #pragma unroll
                for (int j = 0; j < 8; j++)
                    acc[i][j] = fmaf(a[i], bv[j], acc[i][j]);
        }
    }

    float bb[8];
    #pragma unroll
    for (int j = 0; j < 8; j++) bb[j] = bias[c0 + tc * 8 + j];

    #pragma unroll
    for (int i = 0; i < 8; i++) {
        size_t r = (size_t)(r0 + tr * 8 + i);
        float4 o0, o1;
        o0.x = acc[i][0] + bb[0]; o0.y = acc[i][1] + bb[1];
        o0.z = acc[i][2] + bb[2]; o0.w = acc[i][3] + bb[3];
        o1.x = acc[i][4] + bb[4]; o1.y = acc[i][5] + bb[5];
        o1.z = acc[i][6] + bb[6]; o1.w = acc[i][7] + bb[7];
        *(float4*)(out + r * C_ + c0 + tc * 8)     = o0;
        *(float4*)(out + r * C_ + c0 + tc * 8 + 4) = o1;
    }
}

// ============================================================
extern "C" void kernel_launch(void* const* d_in, const int* in_sizes, int n_in,
                              void* d_out, int out_size) {
    const float* x    = (const float*)d_in[0];
    const float* temp = (const float*)d_in[1];
    const float* w    = (const float*)d_in[2];
    const float* bias = (const float*)d_in[3];
    float* out = (float*)d_out;

    qk_kernel<<<dim3(BH_, NSPLIT), 256>>>(x);
    softmax_kernel<<<BH_, 64>>>(temp);
    av_kernel<<<dim3(N_ / 64, BH_), 256>>>(x);
    proj_kernel<<<dim3(C_ / 128, (B_ * N_) / 128), 256>>>(w, bias, out);
}

// round 4
// speedup vs baseline: 1.7540x; 1.7540x over previous
#include <cuda_runtime.h>
#include <cuda_bf16.h>
#include <math.h>
#include <stdint.h>

#define B_   8
#define N_   4096
#define C_   768
#define H_   12
#define D_   64
#define C3_  2304
#define BH_  (B_*H_)
#define NSPLIT 4
#define TOK_PER_SPLIT (N_/NSPLIT)

// ---- scratch (device globals; no runtime allocation allowed) ----
__device__ float g_attn_part[NSPLIT][BH_][D_][D_];
__device__ float g_qnorm_part[NSPLIT][BH_][D_];
__device__ float g_attn[BH_][D_][D_];
__device__ __nv_bfloat16 g_M_hi[B_][C_][C_];          // fused attn*W, hi
__device__ __nv_bfloat16 g_M_lo[B_][C_][C_];          // fused attn*W, lo
__device__ __nv_bfloat16 g_V_hi[(size_t)B_*N_*C_];    // v slice of x, hi
__device__ __nv_bfloat16 g_V_lo[(size_t)B_*N_*C_];    // v slice of x, lo

// ============================================================
// helpers
// ============================================================
__device__ __forceinline__ void cvt2(float a, float b, uint32_t& h, uint32_t& l) {
    __nv_bfloat16 ha = __float2bfloat16_rn(a), hb = __float2bfloat16_rn(b);
    float ra = a - __bfloat162float(ha);
    float rb = b - __bfloat162float(hb);
    __nv_bfloat16 la = __float2bfloat16_rn(ra), lb = __float2bfloat16_rn(rb);
    h = ((uint32_t)__bfloat16_as_ushort(hb) << 16) | (uint32_t)__bfloat16_as_ushort(ha);
    l = ((uint32_t)__bfloat16_as_ushort(lb) << 16) | (uint32_t)__bfloat16_as_ushort(la);
}

__device__ __forceinline__ void mma16816(float c[4],
                                         uint32_t a0, uint32_t a1, uint32_t a2, uint32_t a3,
                                         uint32_t b0, uint32_t b1) {
    asm volatile(
        "mma.sync.aligned.m16n8k16.row.col.f32.bf16.bf16.f32 "
        "{%0,%1,%2,%3}, {%4,%5,%6,%7}, {%8,%9}, {%0,%1,%2,%3};"
        : "+f"(c[0]), "+f"(c[1]), "+f"(c[2]), "+f"(c[3])
        : "r"(a0), "r"(a1), "r"(a2), "r"(a3), "r"(b0), "r"(b1));
}

__device__ __forceinline__ uint32_t smem_u32(const void* p) {
    uint32_t a;
    asm("{ .reg .u64 t; cvta.to.shared.u64 t, %1; cvt.u32.u64 %0, t; }" : "=r"(a) : "l"(p));
    return a;
}

#define CP16(dst, src) \
    asm volatile("cp.async.cg.shared.global [%0], [%1], 16;" :: "r"(dst), "l"(src))
#define CPCOMMIT() asm volatile("cp.async.commit_group;" ::: "memory")
#define CPWAIT2()  asm volatile("cp.async.wait_group 2;" ::: "memory")

// ============================================================
// Kernel 1: per (b,h,split): attn_part = q @ khat^T  (+ Sum q^2 partials)
// ============================================================
__global__ void __launch_bounds__(256) qk_kernel(const float* __restrict__ x) {
    const int bh    = blockIdx.x;
    const int b     = bh / H_;
    const int h     = bh % H_;
    const int split = blockIdx.y;
    const int t     = threadIdx.x;

    const int nl = t >> 4;
    const int j4 = t & 15;
    const int ti = t & 15;
    const int tj = t >> 4;

    __shared__ float qs[16][64];
    __shared__ float ks[16][64];

    float4 qsq = make_float4(0.f, 0.f, 0.f, 0.f);
    float acc[4][4];
    #pragma unroll
    for (int a = 0; a < 4; a++)
        #pragma unroll
        for (int c = 0; c < 4; c++) acc[a][c] = 0.f;

    const float* xb = x + (size_t)b * N_ * C3_ + h * D_;
    const int nbeg = split * TOK_PER_SPLIT;

    for (int n0 = nbeg; n0 < nbeg + TOK_PER_SPLIT; n0 += 16) {
        const float* row = xb + (size_t)(n0 + nl) * C3_;
        float4 q4 = *(const float4*)(row + j4 * 4);
        float4 k4 = *(const float4*)(row + C_ + j4 * 4);

        float s = k4.x*k4.x + k4.y*k4.y + k4.z*k4.z + k4.w*k4.w;
        s += __shfl_xor_sync(0xffffffffu, s, 1);
        s += __shfl_xor_sync(0xffffffffu, s, 2);
        s += __shfl_xor_sync(0xffffffffu, s, 4);
        s += __shfl_xor_sync(0xffffffffu, s, 8);
        float inv = 1.0f / fmaxf(sqrtf(s), 1e-12f);
        k4.x *= inv; k4.y *= inv; k4.z *= inv; k4.w *= inv;

        qsq.x += q4.x*q4.x; qsq.y += q4.y*q4.y;
        qsq.z += q4.z*q4.z; qsq.w += q4.w*q4.w;

        __syncthreads();
        *(float4*)&qs[nl][j4 * 4] = q4;
        *(float4*)&ks[nl][j4 * 4] = k4;
        __syncthreads();

        #pragma unroll
        for (int nn = 0; nn < 16; nn++) {
            float4 aq = *(const float4*)&qs[nn][ti * 4];
            float4 bk = *(const float4*)&ks[nn][tj * 4];
            float aa[4] = {aq.x, aq.y, aq.z, aq.w};
            float bb[4] = {bk.x, bk.y, bk.z, bk.w};
            #pragma unroll
            for (int ii = 0; ii < 4; ii++)
                #pragma unroll
                for (int jj = 0; jj < 4; jj++)
                    acc[ii][jj] = fmaf(aa[ii], bb[jj], acc[ii][jj]);
        }
    }

    #pragma unroll
    for (int ii = 0; ii < 4; ii++)
        #pragma unroll
        for (int jj = 0; jj < 4; jj++)
            g_attn_part[split][bh][ti * 4 + ii][tj * 4 + jj] = acc[ii][jj];

    __shared__ float qn[64];
    if (t < 64) qn[t] = 0.f;
    __syncthreads();
    atomicAdd(&qn[j4 * 4 + 0], qsq.x);
    atomicAdd(&qn[j4 * 4 + 1], qsq.y);
    atomicAdd(&qn[j4 * 4 + 2], qsq.z);
    atomicAdd(&qn[j4 * 4 + 3], qsq.w);
    __syncthreads();
    if (t < 64) g_qnorm_part[split][bh][t] = qn[t];
}

// ============================================================
// Kernel 2: reduce partials, scale, row softmax
// ============================================================
__global__ void __launch_bounds__(64) softmax_kernel(const float* __restrict__ temp) {
    const int bh = blockIdx.x;
    const int h  = bh % H_;
    const int i  = threadIdx.x;

    float qn2 = 0.f;
    #pragma unroll
    for (int s = 0; s < NSPLIT; s++) qn2 += g_qnorm_part[s][bh][i];
    const float invq   = 1.0f / fmaxf(sqrtf(qn2), 1e-12f);
    const float tscale = temp[h] * invq;

    float v[64];
    float mx = -1e30f;
    #pragma unroll
    for (int j = 0; j < 64; j++) {
        float a = 0.f;
        #pragma unroll
        for (int s = 0; s < NSPLIT; s++) a += g_attn_part[s][bh][i][j];
        a *= tscale;
        v[j] = a;
        mx = fmaxf(mx, a);
    }
    float sum = 0.f;
    #pragma unroll
    for (int j = 0; j < 64; j++) { v[j] = expf(v[j] - mx); sum += v[j]; }
    const float r = 1.0f / sum;
    #pragma unroll
    for (int j = 0; j < 64; j++) g_attn[bh][i][j] = v[j] * r;
}

// ============================================================
// Kernel 3: M[b][c'][h*64+j] = sum_i W[c'][h*64+i] * attn[bh][i][j]
//   -> bf16 hi/lo split, K-major (B operand of the big GEMM)
// ============================================================
__global__ void __launch_bounds__(256) mproj_kernel(const float* __restrict__ w) {
    const int bh = blockIdx.x;
    const int b  = bh / H_;
    const int hh = bh % H_;

    __shared__ float as[64][64];
    for (int i = threadIdx.x; i < 4096; i += 256)
        ((float*)as)[i] = ((const float*)g_attn[bh])[i];
    __syncthreads();

    for (int rr = 0; rr < 3; rr++) {
        const int cp = threadIdx.x + rr * 256;
        const float4* wrow = (const float4*)(w + (size_t)cp * C_ + hh * D_);
        float m[64];
        #pragma unroll
        for (int j = 0; j < 64; j++) m[j] = 0.f;

        for (int i4 = 0; i4 < 16; i4++) {
            float4 w4 = wrow[i4];
            float wv[4] = {w4.x, w4.y, w4.z, w4.w};
            #pragma unroll
            for (int s = 0; s < 4; s++) {
                const int i = i4 * 4 + s;
                #pragma unroll
                for (int jv = 0; jv < 16; jv++) {
                    float4 a4 = *(const float4*)&as[i][jv * 4];
                    m[jv*4+0] = fmaf(wv[s], a4.x, m[jv*4+0]);
                    m[jv*4+1] = fmaf(wv[s], a4.y, m[jv*4+1]);
                    m[jv*4+2] = fmaf(wv[s], a4.z, m[jv*4+2]);
                    m[jv*4+3] = fmaf(wv[s], a4.w, m[jv*4+3]);
                }
            }
        }
        #pragma unroll
        for (int p = 0; p < 32; p++) {
            uint32_t hv, lv;
            cvt2(m[2*p], m[2*p+1], hv, lv);
            *(uint32_t*)&g_M_hi[b][cp][hh*64 + 2*p] = hv;
            *(uint32_t*)&g_M_lo[b][cp][hh*64 + 2*p] = lv;
        }
    }
}

// ============================================================
// Kernel 3b: convert V slice of x to bf16 hi/lo (A operand)
// ============================================================
__global__ void __launch_bounds__(256) xvcvt_kernel(const float* __restrict__ x) {
    const size_t f = ((size_t)blockIdx.x * 256 + threadIdx.x) * 4;   // flat [B*N*C]
    const size_t bn = f / C_;
    const int   c  = (int)(f % C_);
    float4 v = *(const float4*)(x + bn * C3_ + 2 * C_ + c);
    uint32_t h0, l0, h1, l1;
    cvt2(v.x, v.y, h0, l0);
    cvt2(v.z, v.w, h1, l1);
    *(uint2*)&g_V_hi[f] = make_uint2(h0, h1);
    *(uint2*)&g_V_lo[f] = make_uint2(l0, l1);
}

// ============================================================
// Kernel 4: out[b,m,c'] = sum_k V[b,m,k]*M[b][c'][k] + bias  (mma.sync bf16 x3)
//   CTA 128x128, 8 warps (2x4), warp tile 64x32, k-step 32, 4-stage cp.async.
// ============================================================
#define KPITCH 40            // bf16 units per smem row (80B, conflict-free)
#define AHIu   0             // offsets in bf16 units within a stage
#define ALOu   5120
#define BHIu   10240
#define BLOu   15360
#define ST_U   20480         // stage size in bf16 units
#define ST_B   40960         // stage size in bytes
#define NSTAGE 4
#define GSMEM  (NSTAGE * ST_B)

__global__ void __launch_bounds__(256, 1)
gemm_kernel(const float* __restrict__ bias, float* __restrict__ out) {
    extern __shared__ __nv_bfloat16 sm[];
    const uint32_t sbase = smem_u32(sm);
    const int t    = threadIdx.x;
    const int lane = t & 31;
    const int warp = t >> 5;
    const int g    = lane >> 2;
    const int tg   = lane & 3;
    const int wm   = warp >> 2;       // 0..1
    const int wn   = warp & 3;        // 0..3
    const int c0   = blockIdx.x * 128;
    const int m0   = blockIdx.y * 128;
    const int b    = blockIdx.z;
    const size_t bn0 = (size_t)b * N_;

    // per-thread cp.async slots: 2 chunks of each of Ahi/Alo/Bhi/Blo
    const int id0 = t * 2, id1 = id0 + 1;
    const int r0 = id0 >> 2, ch0 = id0 & 3;
    const int r1 = id1 >> 2, ch1 = id1 & 3;
    const __nv_bfloat16* aH0 = g_V_hi + (bn0 + m0 + r0) * C_ + ch0 * 8;
    const __nv_bfloat16* aH1 = g_V_hi + (bn0 + m0 + r1) * C_ + ch1 * 8;
    const __nv_bfloat16* aL0 = g_V_lo + (bn0 + m0 + r0) * C_ + ch0 * 8;
    const __nv_bfloat16* aL1 = g_V_lo + (bn0 + m0 + r1) * C_ + ch1 * 8;
    const __nv_bfloat16* bH0 = &g_M_hi[b][c0 + r0][ch0 * 8];
    const __nv_bfloat16* bH1 = &g_M_hi[b][c0 + r1][ch1 * 8];
    const __nv_bfloat16* bL0 = &g_M_lo[b][c0 + r0][ch0 * 8];
    const __nv_bfloat16* bL1 = &g_M_lo[b][c0 + r1][ch1 * 8];
    const uint32_t d0 = (uint32_t)(r0 * 80 + ch0 * 16);
    const uint32_t d1 = (uint32_t)(r1 * 80 + ch1 * 16);

    #define LOADSTAGE(st, k0) do {                                      \
        uint32_t sa = sbase + (uint32_t)(st) * ST_B;                     \
        CP16(sa + AHIu*2 + d0, aH0 + (k0));                              \
        CP16(sa + AHIu*2 + d1, aH1 + (k0));                              \
        CP16(sa + ALOu*2 + d0, aL0 + (k0));                              \
        CP16(sa + ALOu*2 + d1, aL1 + (k0));                              \
        CP16(sa + BHIu*2 + d0, bH0 + (k0));                              \
        CP16(sa + BHIu*2 + d1, bH1 + (k0));                              \
        CP16(sa + BLOu*2 + d0, bL0 + (k0));                              \
        CP16(sa + BLOu*2 + d1, bL1 + (k0));                              \
    } while (0)

    float acc[4][4][4];
    #pragma unroll
    for (int a = 0; a < 4; a++)
        #pragma unroll
        for (int c = 0; c < 4; c++)
            #pragma unroll
            for (int q = 0; q < 4; q++) acc[a][c][q] = 0.f;

    LOADSTAGE(0, 0);  CPCOMMIT();
    LOADSTAGE(1, 32); CPCOMMIT();
    LOADSTAGE(2, 64); CPCOMMIT();

    for (int ks = 0; ks < 24; ks++) {
        CPWAIT2();
        __syncthreads();
        if (ks + 3 < 24) LOADSTAGE((ks + 3) & 3, (ks + 3) * 32);
        CPCOMMIT();

        const __nv_bfloat16* sp = sm + (size_t)(ks & 3) * ST_U;
        #pragma unroll
        for (int kk = 0; kk < 32; kk += 16) {
            #pragma unroll
            for (int pass = 0; pass < 3; pass++) {
                const __nv_bfloat16* ap = sp + (pass == 2 ? ALOu : AHIu);
                const __nv_bfloat16* bp = sp + (pass == 1 ? BLOu : BHIu);
                uint32_t af[4][4], bfr[4][2];
                #pragma unroll
                for (int mi = 0; mi < 4; mi++) {
                    const __nv_bfloat16* a0 =
                        ap + (wm * 64 + mi * 16 + g) * KPITCH + kk + 2 * tg;
                    af[mi][0] = *(const uint32_t*)(a0);
                    af[mi][1] = *(const uint32_t*)(a0 + 8 * KPITCH);
                    af[mi][2] = *(const uint32_t*)(a0 + 8);
                    af[mi][3] = *(const uint32_t*)(a0 + 8 * KPITCH + 8);
                }
                #pragma unroll
                for (int ni = 0; ni < 4; ni++) {
                    const __nv_bfloat16* b0 =
                        bp + (wn * 32 + ni * 8 + g) * KPITCH + kk + 2 * tg;
                    bfr[ni][0] = *(const uint32_t*)(b0);
                    bfr[ni][1] = *(const uint32_t*)(b0 + 8);
                }
                #pragma unroll
                for (int mi = 0; mi < 4; mi++)
                    #pragma unroll
                    for (int ni = 0; ni < 4; ni++)
                        mma16816(acc[mi][ni],
                                 af[mi][0], af[mi][1], af[mi][2], af[mi][3],
                                 bfr[ni][0], bfr[ni][1]);
            }
        }
    }

    // epilogue: bias add + store
    #pragma unroll
    for (int ni = 0; ni < 4; ni++) {
        const int col = wn * 32 + ni * 8 + 2 * tg;
        const float bv0 = bias[c0 + col];
        const float bv1 = bias[c0 + col + 1];
        #pragma unroll
        for (int mi = 0; mi < 4; mi++) {
            const int row = m0 + wm * 64 + mi * 16 + g;
            float* o = out + (bn0 + row) * C_ + c0 + col;
            float2 v0 = make_float2(acc[mi][ni][0] + bv0, acc[mi][ni][1] + bv1);
            float2 v1 = make_float2(acc[mi][ni][2] + bv0, acc[mi][ni][3] + bv1);
            *(float2*)o = v0;
            *(float2*)(o + 8 * C_) = v1;
        }
    }
}

// ============================================================
extern "C" void kernel_launch(void* const* d_in, const int* in_sizes, int n_in,
                              void* d_out, int out_size) {
    const float* x    = (const float*)d_in[0];
    const float* temp = (const float*)d_in[1];
    const float* w    = (const float*)d_in[2];
    const float* bias = (const float*)d_in[3];
    float* out = (float*)d_out;

    cudaFuncSetAttribute(gemm_kernel, cudaFuncAttributeMaxDynamicSharedMemorySize, GSMEM);

    qk_kernel<<<dim3(BH_, NSPLIT), 256>>>(x);
    softmax_kernel<<<BH_, 64>>>(temp);
    mproj_kernel<<<BH_, 256>>>(w);
    xvcvt_kernel<<<(B_ * N_ * C_ / 4) / 256, 256>>>(x);
    gemm_kernel<<<dim3(C_ / 128, N_ / 128, B_), 256, GSMEM>>>(bias, out);
}

// round 5
// speedup vs baseline: 1.8125x; 1.0333x over previous
#include <cuda_runtime.h>
#include <cuda_bf16.h>
#include <math.h>
#include <stdint.h>

#define B_   8
#define N_   4096
#define C_   768
#define H_   12
#define D_   64
#define C3_  2304
#define BH_  (B_*H_)
#define NSPLIT 8
#define TOK_PER_SPLIT (N_/NSPLIT)

// ---- scratch (device globals; no runtime allocation allowed) ----
__device__ float g_attn_part[NSPLIT][BH_][D_][D_];
__device__ float g_qnorm_part[NSPLIT][BH_][D_];
__device__ float g_attn[BH_][D_][D_];
__device__ __nv_bfloat16 g_M_hi[B_][C_][C_];          // fused attn*W, hi
__device__ __nv_bfloat16 g_M_lo[B_][C_][C_];          // fused attn*W, lo
__device__ __nv_bfloat16 g_V_hi[(size_t)B_*N_*C_];    // v slice of x, hi
__device__ __nv_bfloat16 g_V_lo[(size_t)B_*N_*C_];    // v slice of x, lo

// ============================================================
// helpers
// ============================================================
__device__ __forceinline__ void cvt2(float a, float b, uint32_t& h, uint32_t& l) {
    __nv_bfloat16 ha = __float2bfloat16_rn(a), hb = __float2bfloat16_rn(b);
    float ra = a - __bfloat162float(ha);
    float rb = b - __bfloat162float(hb);
    __nv_bfloat16 la = __float2bfloat16_rn(ra), lb = __float2bfloat16_rn(rb);
    h = ((uint32_t)__bfloat16_as_ushort(hb) << 16) | (uint32_t)__bfloat16_as_ushort(ha);
    l = ((uint32_t)__bfloat16_as_ushort(lb) << 16) | (uint32_t)__bfloat16_as_ushort(la);
}

__device__ __forceinline__ void mma16816(float c[4],
                                         const uint32_t a[4],
                                         uint32_t b0, uint32_t b1) {
    asm volatile(
        "mma.sync.aligned.m16n8k16.row.col.f32.bf16.bf16.f32 "
        "{%0,%1,%2,%3}, {%4,%5,%6,%7}, {%8,%9}, {%0,%1,%2,%3};"
        : "+f"(c[0]), "+f"(c[1]), "+f"(c[2]), "+f"(c[3])
        : "r"(a[0]), "r"(a[1]), "r"(a[2]), "r"(a[3]), "r"(b0), "r"(b1));
}

__device__ __forceinline__ uint32_t smem_u32(const void* p) {
    uint32_t a;
    asm("{ .reg .u64 t; cvta.to.shared.u64 t, %1; cvt.u32.u64 %0, t; }" : "=r"(a) : "l"(p));
    return a;
}

#define LDSM4(r, addr) \
    asm volatile("ldmatrix.sync.aligned.m8n8.x4.shared.b16 {%0,%1,%2,%3}, [%4];" \
        : "=r"((r)[0]), "=r"((r)[1]), "=r"((r)[2]), "=r"((r)[3]) : "r"(addr))

#define CP16(dst, src) \
    asm volatile("cp.async.cg.shared.global [%0], [%1], 16;" :: "r"(dst), "l"(src))
#define CPCOMMIT() asm volatile("cp.async.commit_group;" ::: "memory")
#define CPWAIT2()  asm volatile("cp.async.wait_group 2;" ::: "memory")

// ============================================================
// Kernel 1: per (b,h,split): attn_part = q @ khat^T  (+ Sum q^2 partials)
// ============================================================
__global__ void __launch_bounds__(256) qk_kernel(const float* __restrict__ x) {
    const int bh    = blockIdx.x;
    const int b     = bh / H_;
    const int h     = bh % H_;
    const int split = blockIdx.y;
    const int t     = threadIdx.x;

    const int nl = t >> 4;
    const int j4 = t & 15;
    const int ti = t & 15;
    const int tj = t >> 4;

    __shared__ float qs[16][64];
    __shared__ float ks[16][64];

    float4 qsq = make_float4(0.f, 0.f, 0.f, 0.f);
    float acc[4][4];
    #pragma unroll
    for (int a = 0; a < 4; a++)
        #pragma unroll
        for (int c = 0; c < 4; c++) acc[a][c] = 0.f;

    const float* xb = x + (size_t)b * N_ * C3_ + h * D_;
    const int nbeg = split * TOK_PER_SPLIT;

    for (int n0 = nbeg; n0 < nbeg + TOK_PER_SPLIT; n0 += 16) {
        const float* row = xb + (size_t)(n0 + nl) * C3_;
        float4 q4 = *(const float4*)(row + j4 * 4);
        float4 k4 = *(const float4*)(row + C_ + j4 * 4);

        float s = k4.x*k4.x + k4.y*k4.y + k4.z*k4.z + k4.w*k4.w;
        s += __shfl_xor_sync(0xffffffffu, s, 1);
        s += __shfl_xor_sync(0xffffffffu, s, 2);
        s += __shfl_xor_sync(0xffffffffu, s, 4);
        s += __shfl_xor_sync(0xffffffffu, s, 8);
        float inv = 1.0f / fmaxf(sqrtf(s), 1e-12f);
        k4.x *= inv; k4.y *= inv; k4.z *= inv; k4.w *= inv;

        qsq.x += q4.x*q4.x; qsq.y += q4.y*q4.y;
        qsq.z += q4.z*q4.z; qsq.w += q4.w*q4.w;

        __syncthreads();
        *(float4*)&qs[nl][j4 * 4] = q4;
        *(float4*)&ks[nl][j4 * 4] = k4;
        __syncthreads();

        #pragma unroll
        for (int nn = 0; nn < 16; nn++) {
            float4 aq = *(const float4*)&qs[nn][ti * 4];
            float4 bk = *(const float4*)&ks[nn][tj * 4];
            float aa[4] = {aq.x, aq.y, aq.z, aq.w};
            float bb[4] = {bk.x, bk.y, bk.z, bk.w};
            #pragma unroll
            for (int ii = 0; ii < 4; ii++)
                #pragma unroll
                for (int jj = 0; jj < 4; jj++)
                    acc[ii][jj] = fmaf(aa[ii], bb[jj], acc[ii][jj]);
        }
    }

    #pragma unroll
    for (int ii = 0; ii < 4; ii++)
        #pragma unroll
        for (int jj = 0; jj < 4; jj++)
            g_attn_part[split][bh][ti * 4 + ii][tj * 4 + jj] = acc[ii][jj];

    __shared__ float qn[64];
    if (t < 64) qn[t] = 0.f;
    __syncthreads();
    atomicAdd(&qn[j4 * 4 + 0], qsq.x);
    atomicAdd(&qn[j4 * 4 + 1], qsq.y);
    atomicAdd(&qn[j4 * 4 + 2], qsq.z);
    atomicAdd(&qn[j4 * 4 + 3], qsq.w);
    __syncthreads();
    if (t < 64) g_qnorm_part[split][bh][t] = qn[t];
}

// ============================================================
// Kernel 2: reduce partials, scale, row softmax
// ============================================================
__global__ void __launch_bounds__(64) softmax_kernel(const float* __restrict__ temp) {
    const int bh = blockIdx.x;
    const int h  = bh % H_;
    const int i  = threadIdx.x;

    float qn2 = 0.f;
    #pragma unroll
    for (int s = 0; s < NSPLIT; s++) qn2 += g_qnorm_part[s][bh][i];
    const float invq   = 1.0f / fmaxf(sqrtf(qn2), 1e-12f);
    const float tscale = temp[h] * invq;

    float v[64];
    float mx = -1e30f;
    #pragma unroll
    for (int j = 0; j < 64; j++) {
        float a = 0.f;
        #pragma unroll
        for (int s = 0; s < NSPLIT; s++) a += g_attn_part[s][bh][i][j];
        a *= tscale;
        v[j] = a;
        mx = fmaxf(mx, a);
    }
    float sum = 0.f;
    #pragma unroll
    for (int j = 0; j < 64; j++) { v[j] = expf(v[j] - mx); sum += v[j]; }
    const float r = 1.0f / sum;
    #pragma unroll
    for (int j = 0; j < 64; j++) g_attn[bh][i][j] = v[j] * r;
}

// ============================================================
// Kernel 3: M[b][c'][h*64+j] = sum_i W[c'][h*64+i] * attn[bh][i][j]
//   -> bf16 hi/lo split, K-major (B operand of the big GEMM)
// ============================================================
__global__ void __launch_bounds__(256) mproj_kernel(const float* __restrict__ w) {
    const int bh = blockIdx.x;
    const int b  = bh / H_;
    const int hh = bh % H_;

    __shared__ float as[64][64];
    for (int i = threadIdx.x; i < 4096; i += 256)
        ((float*)as)[i] = ((const float*)g_attn[bh])[i];
    __syncthreads();

    for (int rr = 0; rr < 3; rr++) {
        const int cp = threadIdx.x + rr * 256;
        const float4* wrow = (const float4*)(w + (size_t)cp * C_ + hh * D_);
        float m[64];
        #pragma unroll
        for (int j = 0; j < 64; j++) m[j] = 0.f;

        for (int i4 = 0; i4 < 16; i4++) {
            float4 w4 = wrow[i4];
            float wv[4] = {w4.x, w4.y, w4.z, w4.w};
            #pragma unroll
            for (int s = 0; s < 4; s++) {
                const int i = i4 * 4 + s;
                #pragma unroll
                for (int jv = 0; jv < 16; jv++) {
                    float4 a4 = *(const float4*)&as[i][jv * 4];
                    m[jv*4+0] = fmaf(wv[s], a4.x, m[jv*4+0]);
                    m[jv*4+1] = fmaf(wv[s], a4.y, m[jv*4+1]);
                    m[jv*4+2] = fmaf(wv[s], a4.z, m[jv*4+2]);
                    m[jv*4+3] = fmaf(wv[s], a4.w, m[jv*4+3]);
                }
            }
        }
        #pragma unroll
        for (int p = 0; p < 32; p++) {
            uint32_t hv, lv;
            cvt2(m[2*p], m[2*p+1], hv, lv);
            *(uint32_t*)&g_M_hi[b][cp][hh*64 + 2*p] = hv;
            *(uint32_t*)&g_M_lo[b][cp][hh*64 + 2*p] = lv;
        }
    }
}

// ============================================================
// Kernel 3b: convert V slice of x to bf16 hi/lo (A operand)
// ============================================================
__global__ void __launch_bounds__(256) xvcvt_kernel(const float* __restrict__ x) {
    const size_t f = ((size_t)blockIdx.x * 256 + threadIdx.x) * 4;   // flat [B*N*C]
    const size_t bn = f / C_;
    const int   c  = (int)(f % C_);
    float4 v = *(const float4*)(x + bn * C3_ + 2 * C_ + c);
    uint32_t h0, l0, h1, l1;
    cvt2(v.x, v.y, h0, l0);
    cvt2(v.z, v.w, h1, l1);
    *(uint2*)&g_V_hi[f] = make_uint2(h0, h1);
    *(uint2*)&g_V_lo[f] = make_uint2(l0, l1);
}

// ============================================================
// Kernel 4: out[b,m,c'] = sum_k V[b,m,k]*M[b][c'][k] + bias  (mma.sync bf16 x3)
//   CTA 128x128, 8 warps (2x4), warp tile 64x32, k-step 32, 4-stage cp.async,
//   ldmatrix.x4 fragment loads.
// ============================================================
#define KPITCH 40            // bf16 units per smem row (80B, conflict-free)
#define AHI_B  0             // region byte offsets within a stage
#define ALO_B  10240
#define BHI_B  20480
#define BLO_B  30720
#define ST_B   40960         // stage size in bytes
#define NSTAGE 4
#define GSMEM  (NSTAGE * ST_B)

__global__ void __launch_bounds__(256, 1)
gemm_kernel(const float* __restrict__ bias, float* __restrict__ out) {
    extern __shared__ __nv_bfloat16 sm[];
    const uint32_t sbase = smem_u32(sm);
    const int t    = threadIdx.x;
    const int lane = t & 31;
    const int warp = t >> 5;
    const int g    = lane >> 2;
    const int tg   = lane & 3;
    const int wm   = warp >> 2;       // 0..1
    const int wn   = warp & 3;        // 0..3
    const int c0   = blockIdx.x * 128;
    const int m0   = blockIdx.y * 128;
    const int b    = blockIdx.z;
    const size_t bn0 = (size_t)b * N_;

    // per-thread cp.async slots: 2 chunks of each of Ahi/Alo/Bhi/Blo
    const int id0 = t * 2, id1 = id0 + 1;
    const int r0 = id0 >> 2, ch0 = id0 & 3;
    const int r1 = id1 >> 2, ch1 = id1 & 3;
    const __nv_bfloat16* aH0 = g_V_hi + (bn0 + m0 + r0) * C_ + ch0 * 8;
    const __nv_bfloat16* aH1 = g_V_hi + (bn0 + m0 + r1) * C_ + ch1 * 8;
    const __nv_bfloat16* aL0 = g_V_lo + (bn0 + m0 + r0) * C_ + ch0 * 8;
    const __nv_bfloat16* aL1 = g_V_lo + (bn0 + m0 + r1) * C_ + ch1 * 8;
    const __nv_bfloat16* bH0 = &g_M_hi[b][c0 + r0][ch0 * 8];
    const __nv_bfloat16* bH1 = &g_M_hi[b][c0 + r1][ch1 * 8];
    const __nv_bfloat16* bL0 = &g_M_lo[b][c0 + r0][ch0 * 8];
    const __nv_bfloat16* bL1 = &g_M_lo[b][c0 + r1][ch1 * 8];
    const uint32_t d0 = (uint32_t)(r0 * 80 + ch0 * 16);
    const uint32_t d1 = (uint32_t)(r1 * 80 + ch1 * 16);

    #define LOADSTAGE(st, k0) do {                                      \
        uint32_t sa = sbase + (uint32_t)(st) * ST_B;                     \
        CP16(sa + AHI_B + d0, aH0 + (k0));                               \
        CP16(sa + AHI_B + d1, aH1 + (k0));                               \
        CP16(sa + ALO_B + d0, aL0 + (k0));                               \
        CP16(sa + ALO_B + d1, aL1 + (k0));                               \
        CP16(sa + BHI_B + d0, bH0 + (k0));                               \
        CP16(sa + BHI_B + d1, bH1 + (k0));                               \
        CP16(sa + BLO_B + d0, bL0 + (k0));                               \
        CP16(sa + BLO_B + d1, bL1 + (k0));                               \
    } while (0)

    // ldmatrix per-thread byte offsets within a region
    // A x4: lanes 0-7 rows m0-7@k0, 8-15 m8-15@k0, 16-23 m0-7@k8, 24-31 m8-15@k8
    const uint32_t a_off = (uint32_t)(
        (wm * 64 + ((lane >> 3) & 1) * 8 + (lane & 7)) * KPITCH
        + (lane >> 4) * 8) * 2;
    // B x4: lanes 0-7 rows n0-7@k0, 8-15 n0-7@k8, 16-23 n8-15@k0, 24-31 n8-15@k8
    const uint32_t b_off = (uint32_t)(
        (wn * 32 + (lane >> 4) * 8 + (lane & 7)) * KPITCH
        + ((lane >> 3) & 1) * 8) * 2;

    float acc[4][4][4];
    #pragma unroll
    for (int a = 0; a < 4; a++)
        #pragma unroll
        for (int c = 0; c < 4; c++)
            #pragma unroll
            for (int q = 0; q < 4; q++) acc[a][c][q] = 0.f;

    LOADSTAGE(0, 0);  CPCOMMIT();
    LOADSTAGE(1, 32); CPCOMMIT();
    LOADSTAGE(2, 64); CPCOMMIT();

    for (int ks = 0; ks < 24; ks++) {
        CPWAIT2();
        __syncthreads();
        if (ks + 3 < 24) LOADSTAGE((ks + 3) & 3, (ks + 3) * 32);
        CPCOMMIT();

        const uint32_t sp = sbase + (uint32_t)(ks & 3) * ST_B;
        const uint32_t aH = sp + AHI_B + a_off;
        const uint32_t aL = sp + ALO_B + a_off;
        const uint32_t bH = sp + BHI_B + b_off;
        const uint32_t bL = sp + BLO_B + b_off;

        #pragma unroll
        for (int kk = 0; kk < 2; kk++) {
            const uint32_t kb = kk * 32;   // 16 bf16 = 32 bytes
            uint32_t ah[4][4], al[4][4], bh[2][4], bl[2][4];
            #pragma unroll
            for (int mi = 0; mi < 4; mi++) {
                LDSM4(ah[mi], aH + mi * 1280 + kb);
                LDSM4(al[mi], aL + mi * 1280 + kb);
            }
            #pragma unroll
            for (int np = 0; np < 2; np++) {
                LDSM4(bh[np], bH + np * 1280 + kb);
                LDSM4(bl[np], bL + np * 1280 + kb);
            }
            #pragma unroll
            for (int mi = 0; mi < 4; mi++) {
                #pragma unroll
                for (int ni = 0; ni < 4; ni++) {
                    const int np = ni >> 1, ix = (ni & 1) * 2;
                    mma16816(acc[mi][ni], ah[mi], bh[np][ix], bh[np][ix + 1]);
                    mma16816(acc[mi][ni], ah[mi], bl[np][ix], bl[np][ix + 1]);
                    mma16816(acc[mi][ni], al[mi], bh[np][ix], bh[np][ix + 1]);
                }
            }
        }
    }

    // epilogue: bias add + store
    #pragma unroll
    for (int ni = 0; ni < 4; ni++) {
        const int col = wn * 32 + ni * 8 + 2 * tg;
        const float bv0 = bias[c0 + col];
        const float bv1 = bias[c0 + col + 1];
        #pragma unroll
        for (int mi = 0; mi < 4; mi++) {
            const int row = m0 + wm * 64 + mi * 16 + g;
            float* o = out + (bn0 + row) * C_ + c0 + col;
            float2 v0 = make_float2(acc[mi][ni][0] + bv0, acc[mi][ni][1] + bv1);
            float2 v1 = make_float2(acc[mi][ni][2] + bv0, acc[mi][ni][3] + bv1);
            *(float2*)o = v0;
            *(float2*)(o + 8 * C_) = v1;
        }
    }
}

// ============================================================
extern "C" void kernel_launch(void* const* d_in, const int* in_sizes, int n_in,
                              void* d_out, int out_size) {
    const float* x    = (const float*)d_in[0];
    const float* temp = (const float*)d_in[1];
    const float* w    = (const float*)d_in[2];
    const float* bias = (const float*)d_in[3];
    float* out = (float*)d_out;

    cudaFuncSetAttribute(gemm_kernel, cudaFuncAttributeMaxDynamicSharedMemorySize, GSMEM);

    qk_kernel<<<dim3(BH_, NSPLIT), 256>>>(x);
    softmax_kernel<<<BH_, 64>>>(temp);
    mproj_kernel<<<BH_, 256>>>(w);
    xvcvt_kernel<<<(B_ * N_ * C_ / 4) / 256, 256>>>(x);
    gemm_kernel<<<dim3(C_ / 128, N_ / 128, B_), 256, GSMEM>>>(bias, out);
}

// round 6
// speedup vs baseline: 2.9107x; 1.6059x over previous
#include <cuda_runtime.h>
#include <cuda_bf16.h>
#include <cuda_fp16.h>
#include <math.h>
#include <stdint.h>

#define B_   8
#define N_   4096
#define C_   768
#define H_   12
#define D_   64
#define C3_  2304
#define BH_  (B_*H_)
#define NSPLIT 8
#define TOK_PER_SPLIT (N_/NSPLIT)

// ---- scratch (device globals; no runtime allocation allowed) ----
__device__ float g_attn_part[NSPLIT][BH_][D_][D_];
__device__ float g_qnorm_part[NSPLIT][BH_][D_];
__device__ __half g_M[B_][C_][C_];                 // fused attn*W (fp16)
__device__ __half g_V[(size_t)B_*N_*C_];           // v slice of x (fp16)

// ============================================================
// helpers
// ============================================================
__device__ __forceinline__ void mma16816(float c[4],
                                         const uint32_t a[4],
                                         uint32_t b0, uint32_t b1) {
    asm volatile(
        "mma.sync.aligned.m16n8k16.row.col.f32.f16.f16.f32 "
        "{%0,%1,%2,%3}, {%4,%5,%6,%7}, {%8,%9}, {%0,%1,%2,%3};"
        : "+f"(c[0]), "+f"(c[1]), "+f"(c[2]), "+f"(c[3])
        : "r"(a[0]), "r"(a[1]), "r"(a[2]), "r"(a[3]), "r"(b0), "r"(b1));
}

__device__ __forceinline__ uint32_t smem_u32(const void* p) {
    uint32_t a;
    asm("{ .reg .u64 t; cvta.to.shared.u64 t, %1; cvt.u32.u64 %0, t; }" : "=r"(a) : "l"(p));
    return a;
}

#define LDSM4(r, addr) \
    asm volatile("ldmatrix.sync.aligned.m8n8.x4.shared.b16 {%0,%1,%2,%3}, [%4];" \
        : "=r"((r)[0]), "=r"((r)[1]), "=r"((r)[2]), "=r"((r)[3]) : "r"(addr))

#define CP16(dst, src) \
    asm volatile("cp.async.cg.shared.global [%0], [%1], 16;" :: "r"(dst), "l"(src))
#define CPCOMMIT() asm volatile("cp.async.commit_group;" ::: "memory")
#define CPWAIT2()  asm volatile("cp.async.wait_group 2;" ::: "memory")

// ============================================================
// Kernel 1: per (b,h,split): attn_part = q @ khat^T (+ Sum q^2 partials)
// ============================================================
__global__ void __launch_bounds__(256) qk_kernel(const float* __restrict__ x) {
    const int bh    = blockIdx.x;
    const int b     = bh / H_;
    const int h     = bh % H_;
    const int split = blockIdx.y;
    const int t     = threadIdx.x;

    const int nl = t >> 4;
    const int j4 = t & 15;
    const int ti = t & 15;
    const int tj = t >> 4;

    __shared__ float qs[16][64];
    __shared__ float ks[16][64];

    float4 qsq = make_float4(0.f, 0.f, 0.f, 0.f);
    float acc[4][4];
    #pragma unroll
    for (int a = 0; a < 4; a++)
        #pragma unroll
        for (int c = 0; c < 4; c++) acc[a][c] = 0.f;

    const float* xb = x + (size_t)b * N_ * C3_ + h * D_;
    const int nbeg = split * TOK_PER_SPLIT;

    for (int n0 = nbeg; n0 < nbeg + TOK_PER_SPLIT; n0 += 16) {
        const float* row = xb + (size_t)(n0 + nl) * C3_;
        float4 q4 = *(const float4*)(row + j4 * 4);
        float4 k4 = *(const float4*)(row + C_ + j4 * 4);

        float s = k4.x*k4.x + k4.y*k4.y + k4.z*k4.z + k4.w*k4.w;
        s += __shfl_xor_sync(0xffffffffu, s, 1);
        s += __shfl_xor_sync(0xffffffffu, s, 2);
        s += __shfl_xor_sync(0xffffffffu, s, 4);
        s += __shfl_xor_sync(0xffffffffu, s, 8);
        float inv = 1.0f / fmaxf(sqrtf(s), 1e-12f);
        k4.x *= inv; k4.y *= inv; k4.z *= inv; k4.w *= inv;

        qsq.x += q4.x*q4.x; qsq.y += q4.y*q4.y;
        qsq.z += q4.z*q4.z; qsq.w += q4.w*q4.w;

        __syncthreads();
        *(float4*)&qs[nl][j4 * 4] = q4;
        *(float4*)&ks[nl][j4 * 4] = k4;
        __syncthreads();

        #pragma unroll
        for (int nn = 0; nn < 16; nn++) {
            float4 aq = *(const float4*)&qs[nn][ti * 4];
            float4 bk = *(const float4*)&ks[nn][tj * 4];
            float aa[4] = {aq.x, aq.y, aq.z, aq.w};
            float bb[4] = {bk.x, bk.y, bk.z, bk.w};
            #pragma unroll
            for (int ii = 0; ii < 4; ii++)
                #pragma unroll
                for (int jj = 0; jj < 4; jj++)
                    acc[ii][jj] = fmaf(aa[ii], bb[jj], acc[ii][jj]);
        }
    }

    #pragma unroll
    for (int ii = 0; ii < 4; ii++)
        #pragma unroll
        for (int jj = 0; jj < 4; jj++)
            g_attn_part[split][bh][ti * 4 + ii][tj * 4 + jj] = acc[ii][jj];

    __shared__ float qn[64];
    if (t < 64) qn[t] = 0.f;
    __syncthreads();
    atomicAdd(&qn[j4 * 4 + 0], qsq.x);
    atomicAdd(&qn[j4 * 4 + 1], qsq.y);
    atomicAdd(&qn[j4 * 4 + 2], qsq.z);
    atomicAdd(&qn[j4 * 4 + 3], qsq.w);
    __syncthreads();
    if (t < 64) g_qnorm_part[split][bh][t] = qn[t];
}

// ============================================================
// Kernel 2: convert V slice of x to fp16 (A operand)
// ============================================================
__global__ void __launch_bounds__(256) xvcvt_kernel(const float* __restrict__ x) {
    const size_t f = ((size_t)blockIdx.x * 256 + threadIdx.x) * 8;   // flat [B*N*C]
    const size_t bn = f / C_;
    const int   c  = (int)(f % C_);
    const float* p = x + bn * C3_ + 2 * C_ + c;
    float4 v0 = *(const float4*)(p);
    float4 v1 = *(const float4*)(p + 4);
    __half2 h0 = __floats2half2_rn(v0.x, v0.y);
    __half2 h1 = __floats2half2_rn(v0.z, v0.w);
    __half2 h2 = __floats2half2_rn(v1.x, v1.y);
    __half2 h3 = __floats2half2_rn(v1.z, v1.w);
    uint4 o;
    o.x = *(uint32_t*)&h0; o.y = *(uint32_t*)&h1;
    o.z = *(uint32_t*)&h2; o.w = *(uint32_t*)&h3;
    *(uint4*)&g_V[f] = o;
}

// ============================================================
// Kernel 3 (fused softmax + weight fold):
//   softmax rows in-smem, then M[b][c'][h*64+j] = sum_i W[c'][h*64+i]*attn[i][j]
// ============================================================
__global__ void __launch_bounds__(256) mproj_kernel(const float* __restrict__ w,
                                                    const float* __restrict__ temp) {
    const int bh = blockIdx.x;
    const int b  = bh / H_;
    const int hh = bh % H_;
    const int t  = threadIdx.x;

    __shared__ float as[64][64];

    // softmax (threads 0..63, one row each)
    if (t < 64) {
        const int i = t;
        float qn2 = 0.f;
        #pragma unroll
        for (int s = 0; s < NSPLIT; s++) qn2 += g_qnorm_part[s][bh][i];
        const float invq   = 1.0f / fmaxf(sqrtf(qn2), 1e-12f);
        const float tscale = temp[hh] * invq;

        float v[64];
        float mx = -1e30f;
        #pragma unroll
        for (int j = 0; j < 64; j++) {
            float a = 0.f;
            #pragma unroll
            for (int s = 0; s < NSPLIT; s++) a += g_attn_part[s][bh][i][j];
            a *= tscale;
            v[j] = a;
            mx = fmaxf(mx, a);
        }
        float sum = 0.f;
        #pragma unroll
        for (int j = 0; j < 64; j++) { v[j] = expf(v[j] - mx); sum += v[j]; }
        const float r = 1.0f / sum;
        #pragma unroll
        for (int j = 0; j < 64; j++) as[i][j] = v[j] * r;
    }
    __syncthreads();

    for (int rr = 0; rr < 3; rr++) {
        const int cp = t + rr * 256;
        const float4* wrow = (const float4*)(w + (size_t)cp * C_ + hh * D_);
        float m[64];
        #pragma unroll
        for (int j = 0; j < 64; j++) m[j] = 0.f;

        for (int i4 = 0; i4 < 16; i4++) {
            float4 w4 = wrow[i4];
            float wv[4] = {w4.x, w4.y, w4.z, w4.w};
            #pragma unroll
            for (int s = 0; s < 4; s++) {
                const int i = i4 * 4 + s;
                #pragma unroll
                for (int jv = 0; jv < 16; jv++) {
                    float4 a4 = *(const float4*)&as[i][jv * 4];
                    m[jv*4+0] = fmaf(wv[s], a4.x, m[jv*4+0]);
                    m[jv*4+1] = fmaf(wv[s], a4.y, m[jv*4+1]);
                    m[jv*4+2] = fmaf(wv[s], a4.z, m[jv*4+2]);
                    m[jv*4+3] = fmaf(wv[s], a4.w, m[jv*4+3]);
                }
            }
        }
        #pragma unroll
        for (int p = 0; p < 32; p++) {
            __half2 hv = __floats2half2_rn(m[2*p], m[2*p+1]);
            *(uint32_t*)&g_M[b][cp][hh*64 + 2*p] = *(uint32_t*)&hv;
        }
    }
}

// ============================================================
// Kernel 4: out[b,m,c'] = sum_k V[b,m,k]*M[b][c'][k] + bias (fp16 HMMA, 1 pass)
//   CTA 128x128, 8 warps (2x4), warp tile 64x32, k-step 32, 4-stage cp.async,
//   ldmatrix.x4 fragment loads.
// ============================================================
#define KPITCH 40            // fp16 units per smem row (80B, conflict-free)
#define AREG_B 0             // region byte offsets within a stage
#define BREG_B 10240
#define ST_B   20480         // stage size in bytes
#define NSTAGE 4
#define GSMEM  (NSTAGE * ST_B)

__global__ void __launch_bounds__(256, 1)
gemm_kernel(const float* __restrict__ bias, float* __restrict__ out) {
    extern __shared__ __half sm[];
    const uint32_t sbase = smem_u32(sm);
    const int t    = threadIdx.x;
    const int lane = t & 31;
    const int warp = t >> 5;
    const int g    = lane >> 2;
    const int tg   = lane & 3;
    const int wm   = warp >> 2;       // 0..1
    const int wn   = warp & 3;        // 0..3
    const int c0   = blockIdx.x * 128;
    const int m0   = blockIdx.y * 128;
    const int b    = blockIdx.z;
    const size_t bn0 = (size_t)b * N_;

    // per-thread cp.async slots: 2 chunks of A, 2 of B
    const int id0 = t * 2, id1 = id0 + 1;
    const int r0 = id0 >> 2, ch0 = id0 & 3;
    const int r1 = id1 >> 2, ch1 = id1 & 3;
    const __half* aP0 = g_V + (bn0 + m0 + r0) * C_ + ch0 * 8;
    const __half* aP1 = g_V + (bn0 + m0 + r1) * C_ + ch1 * 8;
    const __half* bP0 = &g_M[b][c0 + r0][ch0 * 8];
    const __half* bP1 = &g_M[b][c0 + r1][ch1 * 8];
    const uint32_t d0 = (uint32_t)(r0 * 80 + ch0 * 16);
    const uint32_t d1 = (uint32_t)(r1 * 80 + ch1 * 16);

    #define LOADSTAGE(st, k0) do {                                      \
        uint32_t sa = sbase + (uint32_t)(st) * ST_B;                     \
        CP16(sa + AREG_B + d0, aP0 + (k0));                              \
        CP16(sa + AREG_B + d1, aP1 + (k0));                              \
        CP16(sa + BREG_B + d0, bP0 + (k0));                              \
        CP16(sa + BREG_B + d1, bP1 + (k0));                              \
    } while (0)

    // ldmatrix per-thread byte offsets within a region
    const uint32_t a_off = (uint32_t)(
        (wm * 64 + ((lane >> 3) & 1) * 8 + (lane & 7)) * KPITCH
        + (lane >> 4) * 8) * 2;
    const uint32_t b_off = (uint32_t)(
        (wn * 32 + (lane >> 4) * 8 + (lane & 7)) * KPITCH
        + ((lane >> 3) & 1) * 8) * 2;

    float acc[4][4][4];
    #pragma unroll
    for (int a = 0; a < 4; a++)
        #pragma unroll
        for (int c = 0; c < 4; c++)
            #pragma unroll
            for (int q = 0; q < 4; q++) acc[a][c][q] = 0.f;

    LOADSTAGE(0, 0);  CPCOMMIT();
    LOADSTAGE(1, 32); CPCOMMIT();
    LOADSTAGE(2, 64); CPCOMMIT();

    for (int ks = 0; ks < 24; ks++) {
        CPWAIT2();
        __syncthreads();
        if (ks + 3 < 24) LOADSTAGE((ks + 3) & 3, (ks + 3) * 32);
        CPCOMMIT();

        const uint32_t sp = sbase + (uint32_t)(ks & 3) * ST_B;
        const uint32_t aB = sp + AREG_B + a_off;
        const uint32_t bB = sp + BREG_B + b_off;

        #pragma unroll
        for (int kk = 0; kk < 2; kk++) {
            const uint32_t kb = kk * 32;   // 16 fp16 = 32 bytes
            uint32_t ah[4][4], bh[2][4];
            #pragma unroll
            for (int mi = 0; mi < 4; mi++)
                LDSM4(ah[mi], aB + mi * 1280 + kb);
            #pragma unroll
            for (int np = 0; np < 2; np++)
                LDSM4(bh[np], bB + np * 1280 + kb);
            #pragma unroll
            for (int mi = 0; mi < 4; mi++) {
                #pragma unroll
                for (int ni = 0; ni < 4; ni++) {
                    const int np = ni >> 1, ix = (ni & 1) * 2;
                    mma16816(acc[mi][ni], ah[mi], bh[np][ix], bh[np][ix + 1]);
                }
            }
        }
    }

    // epilogue: bias add + store
    #pragma unroll
    for (int ni = 0; ni < 4; ni++) {
        const int col = wn * 32 + ni * 8 + 2 * tg;
        const float bv0 = bias[c0 + col];
        const float bv1 = bias[c0 + col + 1];
        #pragma unroll
        for (int mi = 0; mi < 4; mi++) {
            const int row = m0 + wm * 64 + mi * 16 + g;
            float* o = out + (bn0 + row) * C_ + c0 + col;
            float2 v0 = make_float2(acc[mi][ni][0] + bv0, acc[mi][ni][1] + bv1);
            float2 v1 = make_float2(acc[mi][ni][2] + bv0, acc[mi][ni][3] + bv1);
            *(float2*)o = v0;
            *(float2*)(o + 8 * C_) = v1;
        }
    }
}

// ============================================================
extern "C" void kernel_launch(void* const* d_in, const int* in_sizes, int n_in,
                              void* d_out, int out_size) {
    const float* x    = (const float*)d_in[0];
    const float* temp = (const float*)d_in[1];
    const float* w    = (const float*)d_in[2];
    const float* bias = (const float*)d_in[3];
    float* out = (float*)d_out;

    cudaFuncSetAttribute(gemm_kernel, cudaFuncAttributeMaxDynamicSharedMemorySize, GSMEM);

    qk_kernel<<<dim3(BH_, NSPLIT), 256>>>(x);
    xvcvt_kernel<<<(B_ * N_ * C_ / 8) / 256, 256>>>(x);
    mproj_kernel<<<BH_, 256>>>(w, temp);
    gemm_kernel<<<dim3(C_ / 128, N_ / 128, B_), 256, GSMEM>>>(bias, out);
}

// round 7
// speedup vs baseline: 3.3174x; 1.1397x over previous
#include <cuda_runtime.h>
#include <cuda_bf16.h>
#include <cuda_fp16.h>
#include <math.h>
#include <stdint.h>

#define B_   8
#define N_   4096
#define C_   768
#define H_   12
#define D_   64
#define C3_  2304
#define BH_  (B_*H_)
#define NSPLIT 8
#define TOK_PER_SPLIT (N_/NSPLIT)   // 512
#define QCH  32                      // tokens per qk chunk
#define NCHUNK (TOK_PER_SPLIT/QCH)   // 16

// ---- scratch (device globals; no runtime allocation allowed) ----
__device__ float g_attn_part[NSPLIT][BH_][D_][D_];
__device__ float g_qnorm_part[NSPLIT][BH_][D_];
__device__ __half g_M[B_][C_][C_];                 // fused attn*W (fp16)
__device__ __half g_V[(size_t)B_*N_*C_];           // v slice of x (fp16)

// ============================================================
// helpers
// ============================================================
__device__ __forceinline__ void mma16816(float c[4],
                                         const uint32_t a[4],
                                         uint32_t b0, uint32_t b1) {
    asm volatile(
        "mma.sync.aligned.m16n8k16.row.col.f32.f16.f16.f32 "
        "{%0,%1,%2,%3}, {%4,%5,%6,%7}, {%8,%9}, {%0,%1,%2,%3};"
        : "+f"(c[0]), "+f"(c[1]), "+f"(c[2]), "+f"(c[3])
        : "r"(a[0]), "r"(a[1]), "r"(a[2]), "r"(a[3]), "r"(b0), "r"(b1));
}

__device__ __forceinline__ uint32_t smem_u32(const void* p) {
    uint32_t a;
    asm("{ .reg .u64 t; cvta.to.shared.u64 t, %1; cvt.u32.u64 %0, t; }" : "=r"(a) : "l"(p));
    return a;
}

#define LDSM4(r, addr) \
    asm volatile("ldmatrix.sync.aligned.m8n8.x4.shared.b16 {%0,%1,%2,%3}, [%4];" \
        : "=r"((r)[0]), "=r"((r)[1]), "=r"((r)[2]), "=r"((r)[3]) : "r"(addr))

#define CP16(dst, src) \
    asm volatile("cp.async.cg.shared.global [%0], [%1], 16;" :: "r"(dst), "l"(src))
#define CPCOMMIT() asm volatile("cp.async.commit_group;" ::: "memory")
#define CPWAIT2()  asm volatile("cp.async.wait_group 2;" ::: "memory")

// ============================================================
// Kernel 1: per (b,h,split): attn_part = q @ khat^T (+ Sum q^2 partials)
//   32-token chunks, double-buffered smem, register prefetch.
//   Loads: 8 threads per token, 8 floats each.
// ============================================================
__global__ void __launch_bounds__(256) qk_kernel(const float* __restrict__ x) {
    const int bh    = blockIdx.x;
    const int b     = bh / H_;
    const int h     = bh % H_;
    const int split = blockIdx.y;
    const int t     = threadIdx.x;

    const int tok = t >> 3;      // token in chunk (0..31)
    const int gi  = t & 7;       // 8-float group within 64 (0..7)
    const int ti  = t & 15;      // output i-quad
    const int tj  = t >> 4;      // output j-quad

    __shared__ float qs[2][QCH][68];
    __shared__ float ks[2][QCH][68];
    __shared__ float qn[64];
    if (t < 64) qn[t] = 0.f;

    float qsq[8];
    #pragma unroll
    for (int i = 0; i < 8; i++) qsq[i] = 0.f;
    float acc[4][4];
    #pragma unroll
    for (int a = 0; a < 4; a++)
        #pragma unroll
        for (int c = 0; c < 4; c++) acc[a][c] = 0.f;

    const float* xb = x + (size_t)b * N_ * C3_ + h * D_ + gi * 8;
    const int nbeg = split * TOK_PER_SPLIT;

    float4 qa, qb, ka, kb;

    #define QK_LOAD(n0) do {                                             \
        const float* row = xb + (size_t)((n0) + tok) * C3_;              \
        qa = *(const float4*)(row);                                      \
        qb = *(const float4*)(row + 4);                                  \
        ka = *(const float4*)(row + C_);                                 \
        kb = *(const float4*)(row + C_ + 4);                             \
    } while (0)

    #define QK_PREP(buf) do {                                            \
        float s = ka.x*ka.x + ka.y*ka.y + ka.z*ka.z + ka.w*ka.w          \
                + kb.x*kb.x + kb.y*kb.y + kb.z*kb.z + kb.w*kb.w;         \
        s += __shfl_xor_sync(0xffffffffu, s, 1);                         \
        s += __shfl_xor_sync(0xffffffffu, s, 2);                         \
        s += __shfl_xor_sync(0xffffffffu, s, 4);                         \
        float inv = 1.0f / fmaxf(sqrtf(s), 1e-12f);                      \
        ka.x *= inv; ka.y *= inv; ka.z *= inv; ka.w *= inv;              \
        kb.x *= inv; kb.y *= inv; kb.z *= inv; kb.w *= inv;              \
        qsq[0] += qa.x*qa.x; qsq[1] += qa.y*qa.y;                        \
        qsq[2] += qa.z*qa.z; qsq[3] += qa.w*qa.w;                        \
        qsq[4] += qb.x*qb.x; qsq[5] += qb.y*qb.y;                        \
        qsq[6] += qb.z*qb.z; qsq[7] += qb.w*qb.w;                        \
        *(float4*)&qs[buf][tok][gi * 8]     = qa;                        \
        *(float4*)&qs[buf][tok][gi * 8 + 4] = qb;                        \
        *(float4*)&ks[buf][tok][gi * 8]     = ka;                        \
        *(float4*)&ks[buf][tok][gi * 8 + 4] = kb;                        \
    } while (0)

    QK_LOAD(nbeg);
    QK_PREP(0);
    __syncthreads();

    for (int c = 0; c < NCHUNK; c++) {
        if (c + 1 < NCHUNK) QK_LOAD(nbeg + (c + 1) * QCH);

        const float (*q)[68] = qs[c & 1];
        const float (*k)[68] = ks[c & 1];
        #pragma unroll
        for (int nn = 0; nn < QCH; nn++) {
            float4 aq = *(const float4*)&q[nn][ti * 4];
            float4 bk = *(const float4*)&k[nn][tj * 4];
            float aa[4] = {aq.x, aq.y, aq.z, aq.w};
            float bb[4] = {bk.x, bk.y, bk.z, bk.w};
            #pragma unroll
            for (int ii = 0; ii < 4; ii++)
                #pragma unroll
                for (int jj = 0; jj < 4; jj++)
                    acc[ii][jj] = fmaf(aa[ii], bb[jj], acc[ii][jj]);
        }

        if (c + 1 < NCHUNK) QK_PREP((c + 1) & 1);
        __syncthreads();
    }

    #pragma unroll
    for (int ii = 0; ii < 4; ii++)
        #pragma unroll
        for (int jj = 0; jj < 4; jj++)
            g_attn_part[split][bh][ti * 4 + ii][tj * 4 + jj] = acc[ii][jj];

    // q^2 partial reduce: lanes with same gi (xor 8, 16), then atomics
    #pragma unroll
    for (int i = 0; i < 8; i++) {
        qsq[i] += __shfl_xor_sync(0xffffffffu, qsq[i], 8);
        qsq[i] += __shfl_xor_sync(0xffffffffu, qsq[i], 16);
    }
    if (((t >> 3) & 3) == 0) {
        #pragma unroll
        for (int i = 0; i < 8; i++)
            atomicAdd(&qn[gi * 8 + i], qsq[i]);
    }
    __syncthreads();
    if (t < 64) g_qnorm_part[split][bh][t] = qn[t];
}

// ============================================================
// Kernel 2: convert V slice of x to fp16 (A operand)
// ============================================================
__global__ void __launch_bounds__(256) xvcvt_kernel(const float* __restrict__ x) {
    const size_t f = ((size_t)blockIdx.x * 256 + threadIdx.x) * 8;   // flat [B*N*C]
    const size_t bn = f / C_;
    const int   c  = (int)(f % C_);
    const float* p = x + bn * C3_ + 2 * C_ + c;
    float4 v0 = *(const float4*)(p);
    float4 v1 = *(const float4*)(p + 4);
    __half2 h0 = __floats2half2_rn(v0.x, v0.y);
    __half2 h1 = __floats2half2_rn(v0.z, v0.w);
    __half2 h2 = __floats2half2_rn(v1.x, v1.y);
    __half2 h3 = __floats2half2_rn(v1.z, v1.w);
    uint4 o;
    o.x = *(uint32_t*)&h0; o.y = *(uint32_t*)&h1;
    o.z = *(uint32_t*)&h2; o.w = *(uint32_t*)&h3;
    *(uint4*)&g_V[f] = o;
}

// ============================================================
// Kernel 3 (fused softmax + weight fold):
//   softmax rows in-smem, then M[b][c'][h*64+j] = sum_i W[c'][h*64+i]*attn[i][j]
// ============================================================
__global__ void __launch_bounds__(256) mproj_kernel(const float* __restrict__ w,
                                                    const float* __restrict__ temp) {
    const int bh = blockIdx.x;
    const int b  = bh / H_;
    const int hh = bh % H_;
    const int t  = threadIdx.x;

    __shared__ float as[64][64];

    if (t < 64) {
        const int i = t;
        float qn2 = 0.f;
        #pragma unroll
        for (int s = 0; s < NSPLIT; s++) qn2 += g_qnorm_part[s][bh][i];
        const float invq   = 1.0f / fmaxf(sqrtf(qn2), 1e-12f);
        const float tscale = temp[hh] * invq;

        float v[64];
        float mx = -1e30f;
        #pragma unroll
        for (int j = 0; j < 64; j++) {
            float a = 0.f;
            #pragma unroll
            for (int s = 0; s < NSPLIT; s++) a += g_attn_part[s][bh][i][j];
            a *= tscale;
            v[j] = a;
            mx = fmaxf(mx, a);
        }
        float sum = 0.f;
        #pragma unroll
        for (int j = 0; j < 64; j++) { v[j] = expf(v[j] - mx); sum += v[j]; }
        const float r = 1.0f / sum;
        #pragma unroll
        for (int j = 0; j < 64; j++) as[i][j] = v[j] * r;
    }
    __syncthreads();

    for (int rr = 0; rr < 3; rr++) {
        const int cp = t + rr * 256;
        const float4* wrow = (const float4*)(w + (size_t)cp * C_ + hh * D_);
        float m[64];
        #pragma unroll
        for (int j = 0; j < 64; j++) m[j] = 0.f;

        for (int i4 = 0; i4 < 16; i4++) {
            float4 w4 = wrow[i4];
            float wv[4] = {w4.x, w4.y, w4.z, w4.w};
            #pragma unroll
            for (int s = 0; s < 4; s++) {
                const int i = i4 * 4 + s;
                #pragma unroll
                for (int jv = 0; jv < 16; jv++) {
                    float4 a4 = *(const float4*)&as[i][jv * 4];
                    m[jv*4+0] = fmaf(wv[s], a4.x, m[jv*4+0]);
                    m[jv*4+1] = fmaf(wv[s], a4.y, m[jv*4+1]);
                    m[jv*4+2] = fmaf(wv[s], a4.z, m[jv*4+2]);
                    m[jv*4+3] = fmaf(wv[s], a4.w, m[jv*4+3]);
                }
            }
        }
        #pragma unroll
        for (int p = 0; p < 32; p++) {
            __half2 hv = __floats2half2_rn(m[2*p], m[2*p+1]);
            *(uint32_t*)&g_M[b][cp][hh*64 + 2*p] = *(uint32_t*)&hv;
        }
    }
}

// ============================================================
// Kernel 4: out[b,m,c'] = sum_k V[b,m,k]*M[b][c'][k] + bias (fp16 HMMA)
//   CTA 128x128, 16 warps (4x4), warp tile 32x32, k-step 32,
//   4-stage cp.async, ldmatrix.x4.
// ============================================================
#define KPITCH 40            // fp16 units per smem row (80B, conflict-free)
#define AREG_B 0             // region byte offsets within a stage
#define BREG_B 10240
#define ST_B   20480         // stage size in bytes
#define NSTAGE 4
#define GSMEM  (NSTAGE * ST_B)

__global__ void __launch_bounds__(512, 1)
gemm_kernel(const float* __restrict__ bias, float* __restrict__ out) {
    extern __shared__ __half sm[];
    const uint32_t sbase = smem_u32(sm);
    const int t    = threadIdx.x;
    const int lane = t & 31;
    const int warp = t >> 5;
    const int g    = lane >> 2;
    const int tg   = lane & 3;
    const int wm   = warp >> 2;       // 0..3
    const int wn   = warp & 3;        // 0..3
    const int c0   = blockIdx.x * 128;
    const int m0   = blockIdx.y * 128;
    const int b    = blockIdx.z;
    const size_t bn0 = (size_t)b * N_;

    // per-thread cp.async slot: 1 chunk of A, 1 of B
    const int r0 = t >> 2, ch0 = t & 3;
    const __half* aP0 = g_V + (bn0 + m0 + r0) * C_ + ch0 * 8;
    const __half* bP0 = &g_M[b][c0 + r0][ch0 * 8];
    const uint32_t d0 = (uint32_t)(r0 * 80 + ch0 * 16);

    #define LOADSTAGE(st, k0) do {                                      \
        uint32_t sa = sbase + (uint32_t)(st) * ST_B;                     \
        CP16(sa + AREG_B + d0, aP0 + (k0));                              \
        CP16(sa + BREG_B + d0, bP0 + (k0));                              \
    } while (0)

    // ldmatrix per-thread byte offsets within a region
    const uint32_t a_off = (uint32_t)(
        (wm * 32 + ((lane >> 3) & 1) * 8 + (lane & 7)) * KPITCH
        + (lane >> 4) * 8) * 2;
    const uint32_t b_off = (uint32_t)(
        (wn * 32 + (lane >> 4) * 8 + (lane & 7)) * KPITCH
        + ((lane >> 3) & 1) * 8) * 2;

    float acc[2][4][4];
    #pragma unroll
    for (int a = 0; a < 2; a++)
        #pragma unroll
        for (int c = 0; c < 4; c++)
            #pragma unroll
            for (int q = 0; q < 4; q++) acc[a][c][q] = 0.f;

    LOADSTAGE(0, 0);  CPCOMMIT();
    LOADSTAGE(1, 32); CPCOMMIT();
    LOADSTAGE(2, 64); CPCOMMIT();

    for (int ks = 0; ks < 24; ks++) {
        CPWAIT2();
        __syncthreads();
        if (ks + 3 < 24) LOADSTAGE((ks + 3) & 3, (ks + 3) * 32);
        CPCOMMIT();

        const uint32_t sp = sbase + (uint32_t)(ks & 3) * ST_B;
        const uint32_t aB = sp + AREG_B + a_off;
        const uint32_t bB = sp + BREG_B + b_off;

        #pragma unroll
        for (int kk = 0; kk < 2; kk++) {
            const uint32_t kb = kk * 32;   // 16 fp16 = 32 bytes
            uint32_t ah[2][4], bh[2][4];
            #pragma unroll
            for (int mi = 0; mi < 2; mi++)
                LDSM4(ah[mi], aB + mi * 1280 + kb);
            #pragma unroll
            for (int np = 0; np < 2; np++)
                LDSM4(bh[np], bB + np * 1280 + kb);
            #pragma unroll
            for (int mi = 0; mi < 2; mi++) {
                #pragma unroll
                for (int ni = 0; ni < 4; ni++) {
                    const int np = ni >> 1, ix = (ni & 1) * 2;
                    mma16816(acc[mi][ni], ah[mi], bh[np][ix], bh[np][ix + 1]);
                }
            }
        }
    }

    // epilogue: bias add + store
    #pragma unroll
    for (int ni = 0; ni < 4; ni++) {
        const int col = wn * 32 + ni * 8 + 2 * tg;
        const float bv0 = bias[c0 + col];
        const float bv1 = bias[c0 + col + 1];
        #pragma unroll
        for (int mi = 0; mi < 2; mi++) {
            const int row = m0 + wm * 32 + mi * 16 + g;
            float* o = out + (bn0 + row) * C_ + c0 + col;
            float2 v0 = make_float2(acc[mi][ni][0] + bv0, acc[mi][ni][1] + bv1);
            float2 v1 = make_float2(acc[mi][ni][2] + bv0, acc[mi][ni][3] + bv1);
            *(float2*)o = v0;
            *(float2*)(o + 8 * C_) = v1;
        }
    }
}

// ============================================================
extern "C" void kernel_launch(void* const* d_in, const int* in_sizes, int n_in,
                              void* d_out, int out_size) {
    const float* x    = (const float*)d_in[0];
    const float* temp = (const float*)d_in[1];
    const float* w    = (const float*)d_in[2];
    const float* bias = (const float*)d_in[3];
    float* out = (float*)d_out;

    cudaFuncSetAttribute(gemm_kernel, cudaFuncAttributeMaxDynamicSharedMemorySize, GSMEM);

    qk_kernel<<<dim3(BH_, NSPLIT), 256>>>(x);
    xvcvt_kernel<<<(B_ * N_ * C_ / 8) / 256, 256>>>(x);
    mproj_kernel<<<BH_, 256>>>(w, temp);
    gemm_kernel<<<dim3(C_ / 128, N_ / 128, B_), 512, GSMEM>>>(bias, out);
}

// round 8
// speedup vs baseline: 3.3189x; 1.0004x over previous
#include <cuda_runtime.h>
#include <cuda_bf16.h>
#include <cuda_fp16.h>
#include <math.h>
#include <stdint.h>

#define B_   8
#define N_   4096
#define C_   768
#define H_   12
#define D_   64
#define C3_  2304
#define BH_  (B_*H_)
#define NSPLIT 8
#define TOK_PER_SPLIT (N_/NSPLIT)   // 512
#define QCH  32                      // tokens per qk chunk
#define NCHUNK (TOK_PER_SPLIT/QCH)   // 16

// ---- scratch (device globals; no runtime allocation allowed) ----
__device__ float g_attn_part[NSPLIT][BH_][D_][D_];
__device__ float g_qnorm_part[NSPLIT][BH_][D_];
__device__ __half g_M[B_][C_][C_];                 // fused attn*W (fp16)
__device__ __half g_V[(size_t)B_*N_*C_];           // v slice of x (fp16)

// ============================================================
// helpers
// ============================================================
__device__ __forceinline__ void mma16816(float c[4],
                                         const uint32_t a[4],
                                         uint32_t b0, uint32_t b1) {
    asm volatile(
        "mma.sync.aligned.m16n8k16.row.col.f32.f16.f16.f32 "
        "{%0,%1,%2,%3}, {%4,%5,%6,%7}, {%8,%9}, {%0,%1,%2,%3};"
        : "+f"(c[0]), "+f"(c[1]), "+f"(c[2]), "+f"(c[3])
        : "r"(a[0]), "r"(a[1]), "r"(a[2]), "r"(a[3]), "r"(b0), "r"(b1));
}

__device__ __forceinline__ uint32_t smem_u32(const void* p) {
    uint32_t a;
    asm("{ .reg .u64 t; cvta.to.shared.u64 t, %1; cvt.u32.u64 %0, t; }" : "=r"(a) : "l"(p));
    return a;
}

#define LDSM4(r, addr) \
    asm volatile("ldmatrix.sync.aligned.m8n8.x4.shared.b16 {%0,%1,%2,%3}, [%4];" \
        : "=r"((r)[0]), "=r"((r)[1]), "=r"((r)[2]), "=r"((r)[3]) : "r"(addr))

#define CP16(dst, src) \
    asm volatile("cp.async.cg.shared.global [%0], [%1], 16;" :: "r"(dst), "l"(src))
#define CPCOMMIT() asm volatile("cp.async.commit_group;" ::: "memory")
#define CPWAIT2()  asm volatile("cp.async.wait_group 2;" ::: "memory")

// ============================================================
// Kernel 1: per (b,h,split): attn_part = q @ khat^T (+ Sum q^2 partials)
//   32-token chunks, double-buffered smem, register prefetch.
//   Loads: 8 threads per token, 8 floats each.
// ============================================================
__global__ void __launch_bounds__(256) qk_kernel(const float* __restrict__ x) {
    const int bh    = blockIdx.x;
    const int b     = bh / H_;
    const int h     = bh % H_;
    const int split = blockIdx.y;
    const int t     = threadIdx.x;

    const int tok = t >> 3;      // token in chunk (0..31)
    const int gi  = t & 7;       // 8-float group within 64 (0..7)
    const int ti  = t & 15;      // output i-quad
    const int tj  = t >> 4;      // output j-quad

    __shared__ float qs[2][QCH][68];
    __shared__ float ks[2][QCH][68];
    __shared__ float qn[64];
    if (t < 64) qn[t] = 0.f;

    float qsq[8];
    #pragma unroll
    for (int i = 0; i < 8; i++) qsq[i] = 0.f;
    float acc[4][4];
    #pragma unroll
    for (int a = 0; a < 4; a++)
        #pragma unroll
        for (int c = 0; c < 4; c++) acc[a][c] = 0.f;

    const float* xb = x + (size_t)b * N_ * C3_ + h * D_ + gi * 8;
    const int nbeg = split * TOK_PER_SPLIT;

    float4 qa, qb, ka, kb;

    #define QK_LOAD(n0) do {                                             \
        const float* row = xb + (size_t)((n0) + tok) * C3_;              \
        qa = *(const float4*)(row);                                      \
        qb = *(const float4*)(row + 4);                                  \
        ka = *(const float4*)(row + C_);                                 \
        kb = *(const float4*)(row + C_ + 4);                             \
    } while (0)

    #define QK_PREP(buf) do {                                            \
        float s = ka.x*ka.x + ka.y*ka.y + ka.z*ka.z + ka.w*ka.w          \
                + kb.x*kb.x + kb.y*kb.y + kb.z*kb.z + kb.w*kb.w;         \
        s += __shfl_xor_sync(0xffffffffu, s, 1);                         \
        s += __shfl_xor_sync(0xffffffffu, s, 2);                         \
        s += __shfl_xor_sync(0xffffffffu, s, 4);                         \
        float inv = 1.0f / fmaxf(sqrtf(s), 1e-12f);                      \
        ka.x *= inv; ka.y *= inv; ka.z *= inv; ka.w *= inv;              \
        kb.x *= inv; kb.y *= inv; kb.z *= inv; kb.w *= inv;              \
        qsq[0] += qa.x*qa.x; qsq[1] += qa.y*qa.y;                        \
        qsq[2] += qa.z*qa.z; qsq[3] += qa.w*qa.w;                        \
        qsq[4] += qb.x*qb.x; qsq[5] += qb.y*qb.y;                        \
        qsq[6] += qb.z*qb.z; qsq[7] += qb.w*qb.w;                        \
        *(float4*)&qs[buf][tok][gi * 8]     = qa;                        \
        *(float4*)&qs[buf][tok][gi * 8 + 4] = qb;                        \
        *(float4*)&ks[buf][tok][gi * 8]     = ka;                        \
        *(float4*)&ks[buf][tok][gi * 8 + 4] = kb;                        \
    } while (0)

    QK_LOAD(nbeg);
    QK_PREP(0);
    __syncthreads();

    for (int c = 0; c < NCHUNK; c++) {
        if (c + 1 < NCHUNK) QK_LOAD(nbeg + (c + 1) * QCH);

        const float (*q)[68] = qs[c & 1];
        const float (*k)[68] = ks[c & 1];
        #pragma unroll
        for (int nn = 0; nn < QCH; nn++) {
            float4 aq = *(const float4*)&q[nn][ti * 4];
            float4 bk = *(const float4*)&k[nn][tj * 4];
            float aa[4] = {aq.x, aq.y, aq.z, aq.w};
            float bb[4] = {bk.x, bk.y, bk.z, bk.w};
            #pragma unroll
            for (int ii = 0; ii < 4; ii++)
                #pragma unroll
                for (int jj = 0; jj < 4; jj++)
                    acc[ii][jj] = fmaf(aa[ii], bb[jj], acc[ii][jj]);
        }

        if (c + 1 < NCHUNK) QK_PREP((c + 1) & 1);
        __syncthreads();
    }

    #pragma unroll
    for (int ii = 0; ii < 4; ii++)
        #pragma unroll
        for (int jj = 0; jj < 4; jj++)
            g_attn_part[split][bh][ti * 4 + ii][tj * 4 + jj] = acc[ii][jj];

    // q^2 partial reduce: lanes with same gi (xor 8, 16), then atomics
    #pragma unroll
    for (int i = 0; i < 8; i++) {
        qsq[i] += __shfl_xor_sync(0xffffffffu, qsq[i], 8);
        qsq[i] += __shfl_xor_sync(0xffffffffu, qsq[i], 16);
    }
    if (((t >> 3) & 3) == 0) {
        #pragma unroll
        for (int i = 0; i < 8; i++)
            atomicAdd(&qn[gi * 8 + i], qsq[i]);
    }
    __syncthreads();
    if (t < 64) g_qnorm_part[split][bh][t] = qn[t];
}

// ============================================================
// Kernel 2: convert V slice of x to fp16 (A operand)
// ============================================================
__global__ void __launch_bounds__(256) xvcvt_kernel(const float* __restrict__ x) {
    const size_t f = ((size_t)blockIdx.x * 256 + threadIdx.x) * 8;   // flat [B*N*C]
    const size_t bn = f / C_;
    const int   c  = (int)(f % C_);
    const float* p = x + bn * C3_ + 2 * C_ + c;
    float4 v0 = *(const float4*)(p);
    float4 v1 = *(const float4*)(p + 4);
    __half2 h0 = __floats2half2_rn(v0.x, v0.y);
    __half2 h1 = __floats2half2_rn(v0.z, v0.w);
    __half2 h2 = __floats2half2_rn(v1.x, v1.y);
    __half2 h3 = __floats2half2_rn(v1.z, v1.w);
    uint4 o;
    o.x = *(uint32_t*)&h0; o.y = *(uint32_t*)&h1;
    o.z = *(uint32_t*)&h2; o.w = *(uint32_t*)&h3;
    *(uint4*)&g_V[f] = o;
}

// ============================================================
// Kernel 3 (fused softmax + weight fold):
//   softmax rows in-smem, then M[b][c'][h*64+j] = sum_i W[c'][h*64+i]*attn[i][j]
// ============================================================
__global__ void __launch_bounds__(256) mproj_kernel(const float* __restrict__ w,
                                                    const float* __restrict__ temp) {
    const int bh = blockIdx.x;
    const int b  = bh / H_;
    const int hh = bh % H_;
    const int t  = threadIdx.x;

    __shared__ float as[64][64];

    if (t < 64) {
        const int i = t;
        float qn2 = 0.f;
        #pragma unroll
        for (int s = 0; s < NSPLIT; s++) qn2 += g_qnorm_part[s][bh][i];
        const float invq   = 1.0f / fmaxf(sqrtf(qn2), 1e-12f);
        const float tscale = temp[hh] * invq;

        float v[64];
        float mx = -1e30f;
        #pragma unroll
        for (int j = 0; j < 64; j++) {
            float a = 0.f;
            #pragma unroll
            for (int s = 0; s < NSPLIT; s++) a += g_attn_part[s][bh][i][j];
            a *= tscale;
            v[j] = a;
            mx = fmaxf(mx, a);
        }
        float sum = 0.f;
        #pragma unroll
        for (int j = 0; j < 64; j++) { v[j] = expf(v[j] - mx); sum += v[j]; }
        const float r = 1.0f / sum;
        #pragma unroll
        for (int j = 0; j < 64; j++) as[i][j] = v[j] * r;
    }
    __syncthreads();

    for (int rr = 0; rr < 3; rr++) {
        const int cp = t + rr * 256;
        const float4* wrow = (const float4*)(w + (size_t)cp * C_ + hh * D_);
        float m[64];
        #pragma unroll
        for (int j = 0; j < 64; j++) m[j] = 0.f;

        for (int i4 = 0; i4 < 16; i4++) {
            float4 w4 = wrow[i4];
            float wv[4] = {w4.x, w4.y, w4.z, w4.w};
            #pragma unroll
            for (int s = 0; s < 4; s++) {
                const int i = i4 * 4 + s;
                #pragma unroll
                for (int jv = 0; jv < 16; jv++) {
                    float4 a4 = *(const float4*)&as[i][jv * 4];
                    m[jv*4+0] = fmaf(wv[s], a4.x, m[jv*4+0]);
                    m[jv*4+1] = fmaf(wv[s], a4.y, m[jv*4+1]);
                    m[jv*4+2] = fmaf(wv[s], a4.z, m[jv*4+2]);
                    m[jv*4+3] = fmaf(wv[s], a4.w, m[jv*4+3]);
                }
            }
        }
        #pragma unroll
        for (int p = 0; p < 32; p++) {
            __half2 hv = __floats2half2_rn(m[2*p], m[2*p+1]);
            *(uint32_t*)&g_M[b][cp][hh*64 + 2*p] = *(uint32_t*)&hv;
        }
    }
}

// ============================================================
// Kernel 4: out[b,m,c'] = sum_k V[b,m,k]*M[b][c'][k] + bias (fp16 HMMA)
//   CTA 128x128, 16 warps (4x4), warp tile 32x32, k-step 32,
//   4-stage cp.async, ldmatrix.x4.
// ============================================================
#define KPITCH 40            // fp16 units per smem row (80B, conflict-free)
#define AREG_B 0             // region byte offsets within a stage
#define BREG_B 10240
#define ST_B   20480         // stage size in bytes
#define NSTAGE 4
#define GSMEM  (NSTAGE * ST_B)

__global__ void __launch_bounds__(512, 1)
gemm_kernel(const float* __restrict__ bias, float* __restrict__ out) {
    extern __shared__ __half sm[];
    const uint32_t sbase = smem_u32(sm);
    const int t    = threadIdx.x;
    const int lane = t & 31;
    const int warp = t >> 5;
    const int g    = lane >> 2;
    const int tg   = lane & 3;
    const int wm   = warp >> 2;       // 0..3
    const int wn   = warp & 3;        // 0..3
    const int c0   = blockIdx.x * 128;
    const int m0   = blockIdx.y * 128;
    const int b    = blockIdx.z;
    const size_t bn0 = (size_t)b * N_;

    // per-thread cp.async slot: 1 chunk of A, 1 of B
    const int r0 = t >> 2, ch0 = t & 3;
    const __half* aP0 = g_V + (bn0 + m0 + r0) * C_ + ch0 * 8;
    const __half* bP0 = &g_M[b][c0 + r0][ch0 * 8];
    const uint32_t d0 = (uint32_t)(r0 * 80 + ch0 * 16);

    #define LOADSTAGE(st, k0) do {                                      \
        uint32_t sa = sbase + (uint32_t)(st) * ST_B;                     \
        CP16(sa + AREG_B + d0, aP0 + (k0));                              \
        CP16(sa + BREG_B + d0, bP0 + (k0));                              \
    } while (0)

    // ldmatrix per-thread byte offsets within a region
    const uint32_t a_off = (uint32_t)(
        (wm * 32 + ((lane >> 3) & 1) * 8 + (lane & 7)) * KPITCH
        + (lane >> 4) * 8) * 2;
    const uint32_t b_off = (uint32_t)(
        (wn * 32 + (lane >> 4) * 8 + (lane & 7)) * KPITCH
        + ((lane >> 3) & 1) * 8) * 2;

    float acc[2][4][4];
    #pragma unroll
    for (int a = 0; a < 2; a++)
        #pragma unroll
        for (int c = 0; c < 4; c++)
            #pragma unroll
            for (int q = 0; q < 4; q++) acc[a][c][q] = 0.f;

    LOADSTAGE(0, 0);  CPCOMMIT();
    LOADSTAGE(1, 32); CPCOMMIT();
    LOADSTAGE(2, 64); CPCOMMIT();

    for (int ks = 0; ks < 24; ks++) {
        CPWAIT2();
        __syncthreads();
        if (ks + 3 < 24) LOADSTAGE((ks + 3) & 3, (ks + 3) * 32);
        CPCOMMIT();

        const uint32_t sp = sbase + (uint32_t)(ks & 3) * ST_B;
        const uint32_t aB = sp + AREG_B + a_off;
        const uint32_t bB = sp + BREG_B + b_off;

        #pragma unroll
        for (int kk = 0; kk < 2; kk++) {
            const uint32_t kb = kk * 32;   // 16 fp16 = 32 bytes
            uint32_t ah[2][4], bh[2][4];
            #pragma unroll
            for (int mi = 0; mi < 2; mi++)
                LDSM4(ah[mi], aB + mi * 1280 + kb);
            #pragma unroll
            for (int np = 0; np < 2; np++)
                LDSM4(bh[np], bB + np * 1280 + kb);
            #pragma unroll
            for (int mi = 0; mi < 2; mi++) {
                #pragma unroll
                for (int ni = 0; ni < 4; ni++) {
                    const int np = ni >> 1, ix = (ni & 1) * 2;
                    mma16816(acc[mi][ni], ah[mi], bh[np][ix], bh[np][ix + 1]);
                }
            }
        }
    }

    // epilogue: bias add + store
    #pragma unroll
    for (int ni = 0; ni < 4; ni++) {
        const int col = wn * 32 + ni * 8 + 2 * tg;
        const float bv0 = bias[c0 + col];
        const float bv1 = bias[c0 + col + 1];
        #pragma unroll
        for (int mi = 0; mi < 2; mi++) {
            const int row = m0 + wm * 32 + mi * 16 + g;
            float* o = out + (bn0 + row) * C_ + c0 + col;
            float2 v0 = make_float2(acc[mi][ni][0] + bv0, acc[mi][ni][1] + bv1);
            float2 v1 = make_float2(acc[mi][ni][2] + bv0, acc[mi][ni][3] + bv1);
            *(float2*)o = v0;
            *(float2*)(o + 8 * C_) = v1;
        }
    }
}

// ============================================================
extern "C" void kernel_launch(void* const* d_in, const int* in_sizes, int n_in,
                              void* d_out, int out_size) {
    const float* x    = (const float*)d_in[0];
    const float* temp = (const float*)d_in[1];
    const float* w    = (const float*)d_in[2];
    const float* bias = (const float*)d_in[3];
    float* out = (float*)d_out;

    cudaFuncSetAttribute(gemm_kernel, cudaFuncAttributeMaxDynamicSharedMemorySize, GSMEM);

    qk_kernel<<<dim3(BH_, NSPLIT), 256>>>(x);
    xvcvt_kernel<<<(B_ * N_ * C_ / 8) / 256, 256>>>(x);
    mproj_kernel<<<BH_, 256>>>(w, temp);
    gemm_kernel<<<dim3(C_ / 128, N_ / 128, B_), 512, GSMEM>>>(bias, out);
}